// round 10
// baseline (speedup 1.0000x reference)
#include <cuda_runtime.h>
#include <cstdint>

// ---------------------------------------------------------------------------
// Problem constants
// ---------------------------------------------------------------------------
#define B_ROWS 4096
#define D_IN   1024
#define H      512
#define NE     16
#define NU     33   // unit 0 = gate, 1..16 = m0 experts, 17..32 = m1 experts

// Scratch (same layout as the passing R2 kernel)
__device__ float g_buf1[(size_t)NU * B_ROWS * H];
__device__ float g_gate2[(size_t)B_ROWS * H];
__device__ float g_dots_part[4 * 32 * B_ROWS];

// SGEMM tiling (identical to R2)
#define BM 128
#define BN 128
#define BK 16
#define TM 8
#define TN 8
#define NTHREADS 256

// Packed fp32x2 FMA (Blackwell family instruction; ptxas never auto-fuses it).
// d = a * b + d, two independent fp32 lanes packed in one 64-bit register.
#define FFMA2(d, a, b) \
    asm("fma.rn.f32x2 %0, %1, %2, %0;" : "+l"(d) : "l"(a), "l"(b))

__device__ __forceinline__ float2 unpack2(unsigned long long v) {
    float2 r;
    r.x = __uint_as_float((unsigned)(v & 0xffffffffu));
    r.y = __uint_as_float((unsigned)(v >> 32));
    return r;
}

// ---------------------------------------------------------------------------
// Layer 1: g_buf1[u] = relu( x @ W1[u] + b1[u] ),  x shared across all units.
// A tile stored DUPLICATED ({a,a}) so packed FMA operands need no packing.
// ---------------------------------------------------------------------------
__global__ __launch_bounds__(NTHREADS)
void layer1_kernel(const float* __restrict__ x,
                   const float* __restrict__ gW,
                   const float* __restrict__ m0W,
                   const float* __restrict__ m1W,
                   const float* __restrict__ gb,
                   const float* __restrict__ m0b,
                   const float* __restrict__ m1b)
{
    const int u = blockIdx.z;
    const int K = D_IN;

    const float* Wbase;
    const float* bias;
    if (u == 0) {
        Wbase = gW;  bias = gb;
    } else if (u <= NE) {
        Wbase = m0W + (size_t)(u - 1) * K * H;
        bias  = m0b + (size_t)(u - 1) * H;
    } else {
        Wbase = m1W + (size_t)(u - 1 - NE) * K * H;
        bias  = m1b + (size_t)(u - 1 - NE) * H;
    }

    float* out = g_buf1 + (size_t)u * B_ROWS * H;

    const int row0 = blockIdx.y * BM;
    const int col0 = blockIdx.x * BN;

    __shared__ float2 As2[BK][BM];       // duplicated: {a, a}   (16 KB)
    __shared__ float2 Bs2[BK][BN / 2];   // adjacent col pairs   (8 KB)

    const int tid = threadIdx.x;
    const int tx = tid & 15;
    const int ty = tid >> 4;

    unsigned long long acc[TM][TN / 2];
#pragma unroll
    for (int i = 0; i < TM; i++)
#pragma unroll
        for (int j = 0; j < TN / 2; j++) acc[i][j] = 0ull;

    for (int k0 = 0; k0 < K; k0 += BK) {
        // A tile: 128 rows x 16 k, duplicated per element
#pragma unroll
        for (int it = 0; it < 2; it++) {
            int idx = tid + it * NTHREADS;   // 0..511 float4 slots
            int r   = idx >> 2;              // 0..127
            int c4  = (idx & 3) * 4;         // 0,4,8,12
            float4 v = *(const float4*)(x + (size_t)(row0 + r) * K + (k0 + c4));
            As2[c4 + 0][r] = make_float2(v.x, v.x);
            As2[c4 + 1][r] = make_float2(v.y, v.y);
            As2[c4 + 2][r] = make_float2(v.z, v.z);
            As2[c4 + 3][r] = make_float2(v.w, v.w);
        }
        // B tile: 16 x 128 from row-major W[K,H], stored as column pairs
#pragma unroll
        for (int it = 0; it < 2; it++) {
            int idx = tid + it * NTHREADS;   // 0..511
            int r   = idx >> 5;              // 0..15
            int c4  = (idx & 31) * 4;        // 0..124
            float4 v = *(const float4*)(Wbase + (size_t)(k0 + r) * H + (col0 + c4));
            Bs2[r][c4 / 2 + 0] = make_float2(v.x, v.y);
            Bs2[r][c4 / 2 + 1] = make_float2(v.z, v.w);
        }
        __syncthreads();

#pragma unroll
        for (int k = 0; k < BK; k++) {
            unsigned long long da[TM], db[TN / 2];
#pragma unroll
            for (int i = 0; i < TM; i++)
                da[i] = *(const unsigned long long*)&As2[k][ty * TM + i];
#pragma unroll
            for (int j = 0; j < TN / 2; j++)
                db[j] = *(const unsigned long long*)&Bs2[k][tx * (TN / 2) + j];
#pragma unroll
            for (int i = 0; i < TM; i++)
#pragma unroll
                for (int j = 0; j < TN / 2; j++)
                    FFMA2(acc[i][j], da[i], db[j]);
        }
        __syncthreads();
    }

    // Epilogue: bias + ReLU
#pragma unroll
    for (int i = 0; i < TM; i++) {
        int m = row0 + ty * TM + i;
#pragma unroll
        for (int j = 0; j < TN / 2; j += 2) {
            int n = col0 + tx * TN + 2 * j;
            float2 p0 = unpack2(acc[i][j]);
            float2 p1 = unpack2(acc[i][j + 1]);
            float4 v;
            v.x = fmaxf(p0.x + bias[n + 0], 0.f);
            v.y = fmaxf(p0.y + bias[n + 1], 0.f);
            v.z = fmaxf(p1.x + bias[n + 2], 0.f);
            v.w = fmaxf(p1.y + bias[n + 3], 0.f);
            *(float4*)(out + (size_t)m * H + n) = v;
        }
    }
}

// ---------------------------------------------------------------------------
// Layer 2: h2 = relu( g_buf1[u] @ W2[u] + b2[u] )
//   u == 0 : store h2 into g_gate2
//   u >= 1 : fused Wo dot -> g_dots_part[blockIdx.x][u-1][row]
// ---------------------------------------------------------------------------
__global__ __launch_bounds__(NTHREADS)
void layer2_kernel(const float* __restrict__ gW,
                   const float* __restrict__ m0W,
                   const float* __restrict__ m1W,
                   const float* __restrict__ gb,
                   const float* __restrict__ m0b,
                   const float* __restrict__ m1b,
                   const float* __restrict__ m0Wo,
                   const float* __restrict__ m1Wo)
{
    const int u = blockIdx.z;
    const int K = H;

    const float* A = g_buf1 + (size_t)u * B_ROWS * H;

    const float* Wbase;
    const float* bias;
    const float* wo = nullptr;
    if (u == 0) {
        Wbase = gW;  bias = gb;
    } else if (u <= NE) {
        Wbase = m0W + (size_t)(u - 1) * K * H;
        bias  = m0b + (size_t)(u - 1) * H;
        wo    = m0Wo + (size_t)(u - 1) * H;
    } else {
        Wbase = m1W + (size_t)(u - 1 - NE) * K * H;
        bias  = m1b + (size_t)(u - 1 - NE) * H;
        wo    = m1Wo + (size_t)(u - 1 - NE) * H;
    }

    const int row0 = blockIdx.y * BM;
    const int col0 = blockIdx.x * BN;

    __shared__ float2 As2[BK][BM];
    __shared__ float2 Bs2[BK][BN / 2];

    const int tid = threadIdx.x;
    const int tx = tid & 15;
    const int ty = tid >> 4;

    unsigned long long acc[TM][TN / 2];
#pragma unroll
    for (int i = 0; i < TM; i++)
#pragma unroll
        for (int j = 0; j < TN / 2; j++) acc[i][j] = 0ull;

    for (int k0 = 0; k0 < K; k0 += BK) {
#pragma unroll
        for (int it = 0; it < 2; it++) {
            int idx = tid + it * NTHREADS;
            int r   = idx >> 2;
            int c4  = (idx & 3) * 4;
            float4 v = *(const float4*)(A + (size_t)(row0 + r) * K + (k0 + c4));
            As2[c4 + 0][r] = make_float2(v.x, v.x);
            As2[c4 + 1][r] = make_float2(v.y, v.y);
            As2[c4 + 2][r] = make_float2(v.z, v.z);
            As2[c4 + 3][r] = make_float2(v.w, v.w);
        }
#pragma unroll
        for (int it = 0; it < 2; it++) {
            int idx = tid + it * NTHREADS;
            int r   = idx >> 5;
            int c4  = (idx & 31) * 4;
            float4 v = *(const float4*)(Wbase + (size_t)(k0 + r) * H + (col0 + c4));
            Bs2[r][c4 / 2 + 0] = make_float2(v.x, v.y);
            Bs2[r][c4 / 2 + 1] = make_float2(v.z, v.w);
        }
        __syncthreads();

#pragma unroll
        for (int k = 0; k < BK; k++) {
            unsigned long long da[TM], db[TN / 2];
#pragma unroll
            for (int i = 0; i < TM; i++)
                da[i] = *(const unsigned long long*)&As2[k][ty * TM + i];
#pragma unroll
            for (int j = 0; j < TN / 2; j++)
                db[j] = *(const unsigned long long*)&Bs2[k][tx * (TN / 2) + j];
#pragma unroll
            for (int i = 0; i < TM; i++)
#pragma unroll
                for (int j = 0; j < TN / 2; j++)
                    FFMA2(acc[i][j], da[i], db[j]);
        }
        __syncthreads();
    }

    if (u == 0) {
        // Gate: store full hidden row tile.
#pragma unroll
        for (int i = 0; i < TM; i++) {
            int m = row0 + ty * TM + i;
#pragma unroll
            for (int j = 0; j < TN / 2; j += 2) {
                int n = col0 + tx * TN + 2 * j;
                float2 p0 = unpack2(acc[i][j]);
                float2 p1 = unpack2(acc[i][j + 1]);
                float4 v;
                v.x = fmaxf(p0.x + bias[n + 0], 0.f);
                v.y = fmaxf(p0.y + bias[n + 1], 0.f);
                v.z = fmaxf(p1.x + bias[n + 2], 0.f);
                v.w = fmaxf(p1.y + bias[n + 3], 0.f);
                *(float4*)(g_gate2 + (size_t)m * H + n) = v;
            }
        }
    } else {
        // Expert: fused dot with Wo over this 128-column tile.
        float part[TM];
#pragma unroll
        for (int i = 0; i < TM; i++) {
            float p = 0.f;
#pragma unroll
            for (int j = 0; j < TN / 2; j++) {
                int n = col0 + tx * TN + 2 * j;
                float2 q = unpack2(acc[i][j]);
                p += fmaxf(q.x + bias[n + 0], 0.f) * wo[n + 0];
                p += fmaxf(q.y + bias[n + 1], 0.f) * wo[n + 1];
            }
            part[i] = p;
        }
        // Reduce across the 16 tx lanes (contiguous lanes, width-16 butterflies).
#pragma unroll
        for (int i = 0; i < TM; i++) {
#pragma unroll
            for (int off = 8; off > 0; off >>= 1)
                part[i] += __shfl_xor_sync(0xffffffffu, part[i], off, 16);
        }
        if (tx == 0) {
#pragma unroll
            for (int i = 0; i < TM; i++) {
                int m = row0 + ty * TM + i;
                g_dots_part[((size_t)blockIdx.x * 32 + (u - 1)) * B_ROWS + m] = part[i];
            }
        }
    }
}

// ---------------------------------------------------------------------------
// Combine: gate logits from g_gate2, softmax, gather dots, weighted sums.
// ---------------------------------------------------------------------------
__global__ __launch_bounds__(128)
void combine_kernel(const float* __restrict__ gWo,   // [512,16]
                    const float* __restrict__ gbo,   // [16]
                    const float* __restrict__ m0bo,  // [16]
                    const float* __restrict__ m1bo,  // [16]
                    float* __restrict__ out)         // [2*4096]
{
    const int b   = blockIdx.x;
    const int tid = threadIdx.x;

    __shared__ float sh[H];
    __shared__ float spart[8][16];
    __shared__ float sw[16];
    __shared__ float sdot[32];

    const float* hg = g_gate2 + (size_t)b * H;
    for (int k = tid; k < H; k += 128) sh[k] = hg[k];

    if (tid < 32) {
        float d = 0.f;
#pragma unroll
        for (int p = 0; p < 4; p++)
            d += g_dots_part[((size_t)p * 32 + tid) * B_ROWS + b];
        d += (tid < NE) ? m0bo[tid] : m1bo[tid - NE];
        sdot[tid] = d;
    }
    __syncthreads();

    {
        int e  = tid & 15;
        int lk = tid >> 4;          // 0..7
        float p = 0.f;
        for (int k = lk; k < H; k += 8)
            p += sh[k] * gWo[k * NE + e];
        spart[lk][e] = p;
    }
    __syncthreads();
    if (tid < 16) {
        float s = gbo[tid];
#pragma unroll
        for (int l = 0; l < 8; l++) s += spart[l][tid];
        sw[tid] = s;
    }
    __syncthreads();
    if (tid == 0) {
        float mx = sw[0];
#pragma unroll
        for (int e = 1; e < 16; e++) mx = fmaxf(mx, sw[e]);
        float ssum = 0.f;
#pragma unroll
        for (int e = 0; e < 16; e++) { float v = expf(sw[e] - mx); sw[e] = v; ssum += v; }
        float inv = 1.f / ssum;

        float a0 = 0.f, a1 = 0.f;
#pragma unroll
        for (int e = 0; e < 16; e++) {
            float w = sw[e] * inv;
            a0 += w * sdot[e];
            a1 += w * sdot[16 + e];
        }
        out[b]          = a0;   // m0
        out[B_ROWS + b] = a1;   // m1
    }
}

extern "C" void kernel_launch(void* const* d_in, const int* in_sizes, int n_in,
                              void* d_out, int out_size)
{
    const float* x    = (const float*)d_in[0];
    const float* m0W1 = (const float*)d_in[1];
    const float* m0b1 = (const float*)d_in[2];
    const float* m0W2 = (const float*)d_in[3];
    const float* m0b2 = (const float*)d_in[4];
    const float* m0Wo = (const float*)d_in[5];
    const float* m0bo = (const float*)d_in[6];
    const float* m1W1 = (const float*)d_in[7];
    const float* m1b1 = (const float*)d_in[8];
    const float* m1W2 = (const float*)d_in[9];
    const float* m1b2 = (const float*)d_in[10];
    const float* m1Wo = (const float*)d_in[11];
    const float* m1bo = (const float*)d_in[12];
    const float* gW1  = (const float*)d_in[13];
    const float* gb1  = (const float*)d_in[14];
    const float* gW2  = (const float*)d_in[15];
    const float* gb2  = (const float*)d_in[16];
    const float* gWo  = (const float*)d_in[17];
    const float* gbo  = (const float*)d_in[18];
    float* out = (float*)d_out;

    dim3 grid(H / BN, B_ROWS / BM, NU);   // (4, 32, 33)

    layer1_kernel<<<grid, NTHREADS>>>(x, gW1, m0W1, m1W1, gb1, m0b1, m1b1);
    layer2_kernel<<<grid, NTHREADS>>>(gW2, m0W2, m1W2, gb2, m0b2, m1b2, m0Wo, m1Wo);
    combine_kernel<<<B_ROWS, 128>>>(gWo, gbo, m0bo, m1bo, out);
}

// round 11
// speedup vs baseline: 1.2645x; 1.2645x over previous
#include <cuda_runtime.h>
#include <cstdint>

// ---------------------------------------------------------------------------
// Problem constants
// ---------------------------------------------------------------------------
#define B_ROWS 4096
#define D_IN   1024
#define H      512
#define NE     16
#define NU     33   // unit 0 = gate, 1..16 = m0 experts, 17..32 = m1 experts

// Scratch
__device__ float g_buf1[(size_t)NU * B_ROWS * H];
__device__ float g_gate2[(size_t)B_ROWS * H];
__device__ float g_dots_part[2 * 32 * B_ROWS];   // [colCTA][unit-1][row]

// Tiling: 128x256 CTA tile, 256 threads, 16x8 per-thread tile.
// ty = warp id (8 warps x 16 rows), tx = lane (32 lanes x 8 cols).
// => every A smem read is a full-warp broadcast (free on the LDS crossbar).
#define BM 128
#define BN 256
#define BK 16
#define TM 16
#define TN 8
#define NTHREADS 256

// ---------------------------------------------------------------------------
// Fused GEMM layer.
//  LAYER 1: g_buf1[u] = relu(x @ W1[u] + b1[u])         (K = 1024)
//  LAYER 2: u==0 -> g_gate2 = relu(h1 @ W2 + b2)
//           u>=1 -> fused Wo dot partials -> g_dots_part (K = 512)
// ---------------------------------------------------------------------------
template <int LAYER>
__global__ __launch_bounds__(NTHREADS)
void layer_kernel(const float* __restrict__ x,
                  const float* __restrict__ gW,
                  const float* __restrict__ m0W,
                  const float* __restrict__ m1W,
                  const float* __restrict__ gb,
                  const float* __restrict__ m0b,
                  const float* __restrict__ m1b,
                  const float* __restrict__ m0Wo,
                  const float* __restrict__ m1Wo)
{
    constexpr int K  = (LAYER == 1) ? D_IN : H;
    constexpr int NT = K / BK;

    const int u    = blockIdx.z;
    const int row0 = blockIdx.y * BM;
    const int col0 = blockIdx.x * BN;

    const float* A;
    if (LAYER == 1) A = x;
    else            A = g_buf1 + (size_t)u * B_ROWS * H;

    const float* Wbase;
    const float* bias;
    const float* wo = nullptr;
    if (u == 0) {
        Wbase = (LAYER == 1) ? gW : gW;   // gW arg carries W1 or W2 per launch
        bias  = gb;
    } else if (u <= NE) {
        Wbase = m0W + (size_t)(u - 1) * K * H;
        bias  = m0b + (size_t)(u - 1) * H;
        if (LAYER == 2) wo = m0Wo + (size_t)(u - 1) * H;
    } else {
        Wbase = m1W + (size_t)(u - 1 - NE) * K * H;
        bias  = m1b + (size_t)(u - 1 - NE) * H;
        if (LAYER == 2) wo = m1Wo + (size_t)(u - 1 - NE) * H;
    }

    __shared__ float As[BK][BM];   // transposed A tile (8 KB)
    __shared__ float Bs[BK][BN];   // B tile            (16 KB)

    const int tid = threadIdx.x;
    const int tx  = tid & 31;      // lane: 8-col group
    const int ty  = tid >> 5;      // warp: 16-row group

    // Loader indices
    const int ar = tid >> 1;                  // wrong granularity; recompute below
    (void)ar;
    // A: 512 float4 slots (2 per thread): slot = tid + it*256
    //    r = slot>>2 (0..127), c4 = (slot&3)*4
    // B: 1024 float4 slots (4 per thread): r = slot>>6 (0..15), c4 = (slot&63)*4

    float acc[TM][TN];
#pragma unroll
    for (int i = 0; i < TM; i++)
#pragma unroll
        for (int j = 0; j < TN; j++) acc[i][j] = 0.f;

    // Register staging for the next tile (software pipeline, no cp.async).
    float4 sa0, sa1, sb0, sb1, sb2, sb3;

    // Prime stage with tile 0
    {
        const int k0 = 0;
        {
            int s = tid;             int r = s >> 2, c4 = (s & 3) * 4;
            sa0 = *(const float4*)(A + (size_t)(row0 + r) * K + k0 + c4);
            s = tid + 256;           r = s >> 2; c4 = (s & 3) * 4;
            sa1 = *(const float4*)(A + (size_t)(row0 + r) * K + k0 + c4);
        }
        {
            int s = tid;             int r = s >> 6, c4 = (s & 63) * 4;
            sb0 = *(const float4*)(Wbase + (size_t)(k0 + r) * H + col0 + c4);
            s = tid + 256;           r = s >> 6; c4 = (s & 63) * 4;
            sb1 = *(const float4*)(Wbase + (size_t)(k0 + r) * H + col0 + c4);
            s = tid + 512;           r = s >> 6; c4 = (s & 63) * 4;
            sb2 = *(const float4*)(Wbase + (size_t)(k0 + r) * H + col0 + c4);
            s = tid + 768;           r = s >> 6; c4 = (s & 63) * 4;
            sb3 = *(const float4*)(Wbase + (size_t)(k0 + r) * H + col0 + c4);
        }
    }

    for (int t = 0; t < NT; t++) {
        // Scatter staged tile into smem
        {
            int s = tid;             int r = s >> 2, c4 = (s & 3) * 4;
            As[c4 + 0][r] = sa0.x; As[c4 + 1][r] = sa0.y;
            As[c4 + 2][r] = sa0.z; As[c4 + 3][r] = sa0.w;
            s = tid + 256;           r = s >> 2; c4 = (s & 3) * 4;
            As[c4 + 0][r] = sa1.x; As[c4 + 1][r] = sa1.y;
            As[c4 + 2][r] = sa1.z; As[c4 + 3][r] = sa1.w;
        }
        {
            int s = tid;             int r = s >> 6, c4 = (s & 63) * 4;
            *(float4*)&Bs[r][c4] = sb0;
            s = tid + 256;           r = s >> 6; c4 = (s & 63) * 4;
            *(float4*)&Bs[r][c4] = sb1;
            s = tid + 512;           r = s >> 6; c4 = (s & 63) * 4;
            *(float4*)&Bs[r][c4] = sb2;
            s = tid + 768;           r = s >> 6; c4 = (s & 63) * 4;
            *(float4*)&Bs[r][c4] = sb3;
        }
        __syncthreads();

        // Prefetch tile t+1 into registers (overlaps with compute below)
        if (t + 1 < NT) {
            const int k0 = (t + 1) * BK;
            {
                int s = tid;         int r = s >> 2, c4 = (s & 3) * 4;
                sa0 = *(const float4*)(A + (size_t)(row0 + r) * K + k0 + c4);
                s = tid + 256;       r = s >> 2; c4 = (s & 3) * 4;
                sa1 = *(const float4*)(A + (size_t)(row0 + r) * K + k0 + c4);
            }
            {
                int s = tid;         int r = s >> 6, c4 = (s & 63) * 4;
                sb0 = *(const float4*)(Wbase + (size_t)(k0 + r) * H + col0 + c4);
                s = tid + 256;       r = s >> 6; c4 = (s & 63) * 4;
                sb1 = *(const float4*)(Wbase + (size_t)(k0 + r) * H + col0 + c4);
                s = tid + 512;       r = s >> 6; c4 = (s & 63) * 4;
                sb2 = *(const float4*)(Wbase + (size_t)(k0 + r) * H + col0 + c4);
                s = tid + 768;       r = s >> 6; c4 = (s & 63) * 4;
                sb3 = *(const float4*)(Wbase + (size_t)(k0 + r) * H + col0 + c4);
            }
        }

        // Compute
#pragma unroll
        for (int k = 0; k < BK; k++) {
            float av[TM], bv[TN];
            *(float4*)&av[0]  = *(const float4*)&As[k][ty * TM + 0];
            *(float4*)&av[4]  = *(const float4*)&As[k][ty * TM + 4];
            *(float4*)&av[8]  = *(const float4*)&As[k][ty * TM + 8];
            *(float4*)&av[12] = *(const float4*)&As[k][ty * TM + 12];
            *(float4*)&bv[0]  = *(const float4*)&Bs[k][tx * TN + 0];
            *(float4*)&bv[4]  = *(const float4*)&Bs[k][tx * TN + 4];
#pragma unroll
            for (int i = 0; i < TM; i++)
#pragma unroll
                for (int j = 0; j < TN; j++)
                    acc[i][j] += av[i] * bv[j];
        }
        __syncthreads();
    }

    // -------------------- Epilogue --------------------
    if (LAYER == 1) {
        float* out = g_buf1 + (size_t)u * B_ROWS * H;
#pragma unroll
        for (int i = 0; i < TM; i++) {
            const int m = row0 + ty * TM + i;
#pragma unroll
            for (int j4 = 0; j4 < TN; j4 += 4) {
                const int n = col0 + tx * TN + j4;
                float4 v;
                v.x = fmaxf(acc[i][j4 + 0] + bias[n + 0], 0.f);
                v.y = fmaxf(acc[i][j4 + 1] + bias[n + 1], 0.f);
                v.z = fmaxf(acc[i][j4 + 2] + bias[n + 2], 0.f);
                v.w = fmaxf(acc[i][j4 + 3] + bias[n + 3], 0.f);
                *(float4*)(out + (size_t)m * H + n) = v;
            }
        }
    } else if (u == 0) {
#pragma unroll
        for (int i = 0; i < TM; i++) {
            const int m = row0 + ty * TM + i;
#pragma unroll
            for (int j4 = 0; j4 < TN; j4 += 4) {
                const int n = col0 + tx * TN + j4;
                float4 v;
                v.x = fmaxf(acc[i][j4 + 0] + bias[n + 0], 0.f);
                v.y = fmaxf(acc[i][j4 + 1] + bias[n + 1], 0.f);
                v.z = fmaxf(acc[i][j4 + 2] + bias[n + 2], 0.f);
                v.w = fmaxf(acc[i][j4 + 3] + bias[n + 3], 0.f);
                *(float4*)(g_gate2 + (size_t)m * H + n) = v;
            }
        }
    } else {
        // Fused Wo dot across this CTA's 256 columns.
#pragma unroll
        for (int i = 0; i < TM; i++) {
            float d = 0.f;
#pragma unroll
            for (int j = 0; j < TN; j++) {
                const int n = col0 + tx * TN + j;
                d += fmaxf(acc[i][j] + bias[n], 0.f) * wo[n];
            }
            // Full-warp reduction (all 32 lanes share the same row set)
            d += __shfl_xor_sync(0xffffffffu, d, 16);
            d += __shfl_xor_sync(0xffffffffu, d, 8);
            d += __shfl_xor_sync(0xffffffffu, d, 4);
            d += __shfl_xor_sync(0xffffffffu, d, 2);
            d += __shfl_xor_sync(0xffffffffu, d, 1);
            if (tx == 0) {
                const int m = row0 + ty * TM + i;
                g_dots_part[((size_t)blockIdx.x * 32 + (u - 1)) * B_ROWS + m] = d;
            }
        }
    }
}

// ---------------------------------------------------------------------------
// Combine: gate logits + softmax + weighted sum of expert dots.
// ---------------------------------------------------------------------------
__global__ __launch_bounds__(128)
void combine_kernel(const float* __restrict__ gWo,   // [512,16]
                    const float* __restrict__ gbo,   // [16]
                    const float* __restrict__ m0bo,  // [16]
                    const float* __restrict__ m1bo,  // [16]
                    float* __restrict__ out)         // [2*4096]
{
    const int b   = blockIdx.x;
    const int tid = threadIdx.x;

    __shared__ float sh[H];
    __shared__ float spart[8][16];
    __shared__ float sw[16];
    __shared__ float sdot[32];

    const float* hg = g_gate2 + (size_t)b * H;
    for (int k = tid; k < H; k += 128) sh[k] = hg[k];

    if (tid < 32) {
        float d = g_dots_part[((size_t)0 * 32 + tid) * B_ROWS + b]
                + g_dots_part[((size_t)1 * 32 + tid) * B_ROWS + b];
        d += (tid < NE) ? m0bo[tid] : m1bo[tid - NE];
        sdot[tid] = d;
    }
    __syncthreads();

    {
        int e  = tid & 15;
        int lk = tid >> 4;          // 0..7
        float p = 0.f;
        for (int k = lk; k < H; k += 8)
            p += sh[k] * gWo[k * NE + e];
        spart[lk][e] = p;
    }
    __syncthreads();
    if (tid < 16) {
        float s = gbo[tid];
#pragma unroll
        for (int l = 0; l < 8; l++) s += spart[l][tid];
        sw[tid] = s;
    }
    __syncthreads();
    if (tid == 0) {
        float mx = sw[0];
#pragma unroll
        for (int e = 1; e < 16; e++) mx = fmaxf(mx, sw[e]);
        float ssum = 0.f;
#pragma unroll
        for (int e = 0; e < 16; e++) { float v = expf(sw[e] - mx); sw[e] = v; ssum += v; }
        float inv = 1.f / ssum;

        float a0 = 0.f, a1 = 0.f;
#pragma unroll
        for (int e = 0; e < 16; e++) {
            float w = sw[e] * inv;
            a0 += w * sdot[e];
            a1 += w * sdot[16 + e];
        }
        out[b]          = a0;   // m0
        out[B_ROWS + b] = a1;   // m1
    }
}

extern "C" void kernel_launch(void* const* d_in, const int* in_sizes, int n_in,
                              void* d_out, int out_size)
{
    const float* x    = (const float*)d_in[0];
    const float* m0W1 = (const float*)d_in[1];
    const float* m0b1 = (const float*)d_in[2];
    const float* m0W2 = (const float*)d_in[3];
    const float* m0b2 = (const float*)d_in[4];
    const float* m0Wo = (const float*)d_in[5];
    const float* m0bo = (const float*)d_in[6];
    const float* m1W1 = (const float*)d_in[7];
    const float* m1b1 = (const float*)d_in[8];
    const float* m1W2 = (const float*)d_in[9];
    const float* m1b2 = (const float*)d_in[10];
    const float* m1Wo = (const float*)d_in[11];
    const float* m1bo = (const float*)d_in[12];
    const float* gW1  = (const float*)d_in[13];
    const float* gb1  = (const float*)d_in[14];
    const float* gW2  = (const float*)d_in[15];
    const float* gb2  = (const float*)d_in[16];
    const float* gWo  = (const float*)d_in[17];
    const float* gbo  = (const float*)d_in[18];
    float* out = (float*)d_out;

    dim3 grid(H / BN, B_ROWS / BM, NU);   // (2, 32, 33)

    layer_kernel<1><<<grid, NTHREADS>>>(x, gW1, m0W1, m1W1, gb1, m0b1, m1b1,
                                        nullptr, nullptr);
    layer_kernel<2><<<grid, NTHREADS>>>(x, gW2, m0W2, m1W2, gb2, m0b2, m1b2,
                                        m0Wo, m1Wo);
    combine_kernel<<<B_ROWS, 128>>>(gWo, gbo, m0bo, m1bo, out);
}

// round 12
// speedup vs baseline: 1.3161x; 1.0408x over previous
#include <cuda_runtime.h>
#include <cstdint>

// ---------------------------------------------------------------------------
// Problem constants
// ---------------------------------------------------------------------------
#define B_ROWS 4096
#define D_IN   1024
#define H      512
#define NE     16
#define NU     33   // unit 0 = gate, 1..16 = m0 experts, 17..32 = m1 experts

// Scratch
__device__ float g_buf1[(size_t)NU * B_ROWS * H];
__device__ float g_gate2[(size_t)B_ROWS * H];
__device__ float g_dots_part[2 * 32 * B_ROWS];   // [colCTA][unit-1][row]

// Tiling: 64x256 CTA tile, 256 threads (8 warps), 8x8 per-thread tile.
// ty = warp id (8 warps x 8 rows)  -> A smem reads are full-warp broadcasts.
// Lane tx owns cols {tx*4..+3} and {128+tx*4..+3} -> both B reads are
// lane-contiguous LDS.128 (4 wavefronts each, no conflicts).
#define BM 64
#define BN 256
#define BK 16
#define TM 8
#define TN 8
#define NTHREADS 256

// ---------------------------------------------------------------------------
// Fused GEMM layer.
//  LAYER 1: g_buf1[u] = relu(x @ W1[u] + b1[u])         (K = 1024)
//  LAYER 2: u==0 -> g_gate2 = relu(h1 @ W2 + b2)
//           u>=1 -> fused Wo dot partials -> g_dots_part (K = 512)
// ---------------------------------------------------------------------------
template <int LAYER>
__global__ __launch_bounds__(NTHREADS, 2)
void layer_kernel(const float* __restrict__ x,
                  const float* __restrict__ gW,
                  const float* __restrict__ m0W,
                  const float* __restrict__ m1W,
                  const float* __restrict__ gb,
                  const float* __restrict__ m0b,
                  const float* __restrict__ m1b,
                  const float* __restrict__ m0Wo,
                  const float* __restrict__ m1Wo)
{
    constexpr int K  = (LAYER == 1) ? D_IN : H;
    constexpr int NT = K / BK;

    const int u    = blockIdx.z;
    const int row0 = blockIdx.y * BM;
    const int col0 = blockIdx.x * BN;

    const float* A;
    if (LAYER == 1) A = x;
    else            A = g_buf1 + (size_t)u * B_ROWS * H;

    const float* Wbase;
    const float* bias;
    const float* wo = nullptr;
    if (u == 0) {
        Wbase = gW;
        bias  = gb;
    } else if (u <= NE) {
        Wbase = m0W + (size_t)(u - 1) * K * H;
        bias  = m0b + (size_t)(u - 1) * H;
        if (LAYER == 2) wo = m0Wo + (size_t)(u - 1) * H;
    } else {
        Wbase = m1W + (size_t)(u - 1 - NE) * K * H;
        bias  = m1b + (size_t)(u - 1 - NE) * H;
        if (LAYER == 2) wo = m1Wo + (size_t)(u - 1 - NE) * H;
    }

    __shared__ float As[BK][BM];   // transposed A tile (4 KB)
    __shared__ float Bs[BK][BN];   // B tile            (16 KB)

    const int tid = threadIdx.x;
    const int tx  = tid & 31;      // lane
    const int ty  = tid >> 5;      // warp -> 8-row group

    float acc[TM][TN];
#pragma unroll
    for (int i = 0; i < TM; i++)
#pragma unroll
        for (int j = 0; j < TN; j++) acc[i][j] = 0.f;

    // Loader indices:
    // A: 256 float4 slots (1/thread): r = tid>>2 (0..63), c4 = (tid&3)*4
    // B: 1024 float4 slots (4/thread): slot = tid + it*256,
    //    r = slot>>6 (0..15), c4 = (slot&63)*4
    const int a_r  = tid >> 2;
    const int a_c4 = (tid & 3) * 4;

    // Register staging for the next tile.
    float4 sa, sb0, sb1, sb2, sb3;

    // Prime stage with tile 0
    {
        sa = *(const float4*)(A + (size_t)(row0 + a_r) * K + a_c4);
        int s = tid;        int r = s >> 6, c4 = (s & 63) * 4;
        sb0 = *(const float4*)(Wbase + (size_t)r * H + col0 + c4);
        s = tid + 256;      r = s >> 6; c4 = (s & 63) * 4;
        sb1 = *(const float4*)(Wbase + (size_t)r * H + col0 + c4);
        s = tid + 512;      r = s >> 6; c4 = (s & 63) * 4;
        sb2 = *(const float4*)(Wbase + (size_t)r * H + col0 + c4);
        s = tid + 768;      r = s >> 6; c4 = (s & 63) * 4;
        sb3 = *(const float4*)(Wbase + (size_t)r * H + col0 + c4);
    }

    for (int t = 0; t < NT; t++) {
        // Scatter staged tile into smem
        As[a_c4 + 0][a_r] = sa.x;
        As[a_c4 + 1][a_r] = sa.y;
        As[a_c4 + 2][a_r] = sa.z;
        As[a_c4 + 3][a_r] = sa.w;
        {
            int s = tid;        int r = s >> 6, c4 = (s & 63) * 4;
            *(float4*)&Bs[r][c4] = sb0;
            s = tid + 256;      r = s >> 6; c4 = (s & 63) * 4;
            *(float4*)&Bs[r][c4] = sb1;
            s = tid + 512;      r = s >> 6; c4 = (s & 63) * 4;
            *(float4*)&Bs[r][c4] = sb2;
            s = tid + 768;      r = s >> 6; c4 = (s & 63) * 4;
            *(float4*)&Bs[r][c4] = sb3;
        }
        __syncthreads();

        // Prefetch tile t+1 into registers (overlaps with compute below)
        if (t + 1 < NT) {
            const int k0 = (t + 1) * BK;
            sa = *(const float4*)(A + (size_t)(row0 + a_r) * K + k0 + a_c4);
            int s = tid;        int r = s >> 6, c4 = (s & 63) * 4;
            sb0 = *(const float4*)(Wbase + (size_t)(k0 + r) * H + col0 + c4);
            s = tid + 256;      r = s >> 6; c4 = (s & 63) * 4;
            sb1 = *(const float4*)(Wbase + (size_t)(k0 + r) * H + col0 + c4);
            s = tid + 512;      r = s >> 6; c4 = (s & 63) * 4;
            sb2 = *(const float4*)(Wbase + (size_t)(k0 + r) * H + col0 + c4);
            s = tid + 768;      r = s >> 6; c4 = (s & 63) * 4;
            sb3 = *(const float4*)(Wbase + (size_t)(k0 + r) * H + col0 + c4);
        }

        // Compute: warp-uniform A reads, lane-contiguous B reads.
#pragma unroll
        for (int k = 0; k < BK; k++) {
            float av[TM], bv[TN];
            *(float4*)&av[0] = *(const float4*)&As[k][ty * TM + 0];
            *(float4*)&av[4] = *(const float4*)&As[k][ty * TM + 4];
            *(float4*)&bv[0] = *(const float4*)&Bs[k][tx * 4];
            *(float4*)&bv[4] = *(const float4*)&Bs[k][128 + tx * 4];
#pragma unroll
            for (int i = 0; i < TM; i++)
#pragma unroll
                for (int j = 0; j < TN; j++)
                    acc[i][j] += av[i] * bv[j];
        }
        __syncthreads();
    }

    // -------------------- Epilogue --------------------
    // Column mapping: acc[i][0..3] -> cols col0 + tx*4 + j
    //                 acc[i][4..7] -> cols col0 + 128 + tx*4 + (j-4)
    if (LAYER == 1 || u == 0) {
        float* out = (LAYER == 1) ? (g_buf1 + (size_t)u * B_ROWS * H) : g_gate2;
#pragma unroll
        for (int i = 0; i < TM; i++) {
            const int m = row0 + ty * TM + i;
#pragma unroll
            for (int g = 0; g < 2; g++) {
                const int n = col0 + g * 128 + tx * 4;
                float4 v;
                v.x = fmaxf(acc[i][g * 4 + 0] + bias[n + 0], 0.f);
                v.y = fmaxf(acc[i][g * 4 + 1] + bias[n + 1], 0.f);
                v.z = fmaxf(acc[i][g * 4 + 2] + bias[n + 2], 0.f);
                v.w = fmaxf(acc[i][g * 4 + 3] + bias[n + 3], 0.f);
                *(float4*)(out + (size_t)m * H + n) = v;
            }
        }
    } else {
        // Fused Wo dot across this CTA's 256 columns.
#pragma unroll
        for (int i = 0; i < TM; i++) {
            float d = 0.f;
#pragma unroll
            for (int g = 0; g < 2; g++) {
#pragma unroll
                for (int j = 0; j < 4; j++) {
                    const int n = col0 + g * 128 + tx * 4 + j;
                    d += fmaxf(acc[i][g * 4 + j] + bias[n], 0.f) * wo[n];
                }
            }
            // Full-warp reduction (all lanes share this row)
            d += __shfl_xor_sync(0xffffffffu, d, 16);
            d += __shfl_xor_sync(0xffffffffu, d, 8);
            d += __shfl_xor_sync(0xffffffffu, d, 4);
            d += __shfl_xor_sync(0xffffffffu, d, 2);
            d += __shfl_xor_sync(0xffffffffu, d, 1);
            if (tx == 0) {
                const int m = row0 + ty * TM + i;
                g_dots_part[((size_t)blockIdx.x * 32 + (u - 1)) * B_ROWS + m] = d;
            }
        }
    }
}

// ---------------------------------------------------------------------------
// Combine: gate logits + softmax + weighted sum of expert dots.
// ---------------------------------------------------------------------------
__global__ __launch_bounds__(128)
void combine_kernel(const float* __restrict__ gWo,   // [512,16]
                    const float* __restrict__ gbo,   // [16]
                    const float* __restrict__ m0bo,  // [16]
                    const float* __restrict__ m1bo,  // [16]
                    float* __restrict__ out)         // [2*4096]
{
    const int b   = blockIdx.x;
    const int tid = threadIdx.x;

    __shared__ float sh[H];
    __shared__ float spart[8][16];
    __shared__ float sw[16];
    __shared__ float sdot[32];

    const float* hg = g_gate2 + (size_t)b * H;
    for (int k = tid; k < H; k += 128) sh[k] = hg[k];

    if (tid < 32) {
        float d = g_dots_part[((size_t)0 * 32 + tid) * B_ROWS + b]
                + g_dots_part[((size_t)1 * 32 + tid) * B_ROWS + b];
        d += (tid < NE) ? m0bo[tid] : m1bo[tid - NE];
        sdot[tid] = d;
    }
    __syncthreads();

    {
        int e  = tid & 15;
        int lk = tid >> 4;          // 0..7
        float p = 0.f;
        for (int k = lk; k < H; k += 8)
            p += sh[k] * gWo[k * NE + e];
        spart[lk][e] = p;
    }
    __syncthreads();
    if (tid < 16) {
        float s = gbo[tid];
#pragma unroll
        for (int l = 0; l < 8; l++) s += spart[l][tid];
        sw[tid] = s;
    }
    __syncthreads();
    if (tid == 0) {
        float mx = sw[0];
#pragma unroll
        for (int e = 1; e < 16; e++) mx = fmaxf(mx, sw[e]);
        float ssum = 0.f;
#pragma unroll
        for (int e = 0; e < 16; e++) { float v = expf(sw[e] - mx); sw[e] = v; ssum += v; }
        float inv = 1.f / ssum;

        float a0 = 0.f, a1 = 0.f;
#pragma unroll
        for (int e = 0; e < 16; e++) {
            float w = sw[e] * inv;
            a0 += w * sdot[e];
            a1 += w * sdot[16 + e];
        }
        out[b]          = a0;   // m0
        out[B_ROWS + b] = a1;   // m1
    }
}

extern "C" void kernel_launch(void* const* d_in, const int* in_sizes, int n_in,
                              void* d_out, int out_size)
{
    const float* x    = (const float*)d_in[0];
    const float* m0W1 = (const float*)d_in[1];
    const float* m0b1 = (const float*)d_in[2];
    const float* m0W2 = (const float*)d_in[3];
    const float* m0b2 = (const float*)d_in[4];
    const float* m0Wo = (const float*)d_in[5];
    const float* m0bo = (const float*)d_in[6];
    const float* m1W1 = (const float*)d_in[7];
    const float* m1b1 = (const float*)d_in[8];
    const float* m1W2 = (const float*)d_in[9];
    const float* m1b2 = (const float*)d_in[10];
    const float* m1Wo = (const float*)d_in[11];
    const float* m1bo = (const float*)d_in[12];
    const float* gW1  = (const float*)d_in[13];
    const float* gb1  = (const float*)d_in[14];
    const float* gW2  = (const float*)d_in[15];
    const float* gb2  = (const float*)d_in[16];
    const float* gWo  = (const float*)d_in[17];
    const float* gbo  = (const float*)d_in[18];
    float* out = (float*)d_out;

    dim3 grid(H / BN, B_ROWS / BM, NU);   // (2, 64, 33)

    layer_kernel<1><<<grid, NTHREADS>>>(x, gW1, m0W1, m1W1, gb1, m0b1, m1b1,
                                        nullptr, nullptr);
    layer_kernel<2><<<grid, NTHREADS>>>(x, gW2, m0W2, m1W2, gb2, m0b2, m1b2,
                                        m0Wo, m1Wo);
    combine_kernel<<<B_ROWS, 128>>>(gWo, gbo, m0bo, m1bo, out);
}